// round 10
// baseline (speedup 1.0000x reference)
#include <cuda_runtime.h>
#include <math.h>

#define BATCH 256
#define DI    5120
#define RNK   160
#define NS    16
#define RX    192            // 160 (delta) + 16 (B) + 16 (C)

#define KS1   40             // split-K factor for GEMM1
#define KCH   (DI / KS1)     // 128
#define BT1   16             // batch tile GEMM1
#define WCH   16             // w prefetch chunk GEMM1

#define BTF   16             // batch tile fused kernel
#define DCHF  128            // d's per fused block
#define RCHF  16             // Wdt smem chunk (rows)

#define LOG2E 1.4426950408889634f

// ---- scratch (no dynamic allocation allowed) ----
__device__ float g_part[KS1 * BATCH * RX];   // GEMM1 split-K partials
__device__ float g_xd[BATCH * RX];           // [xd | Bp | C]
__device__ float g_negA[DI * NS];            // [d][n]: -exp(A_log)*log2e

__device__ __forceinline__ float ex2(float v) {
    float r;
    asm("ex2.approx.ftz.f32 %0, %1;" : "=f"(r) : "f"(v));
    return r;
}

// ---------------------------------------------------------------- prep
__global__ void k_prep(const float* __restrict__ A_log) {
    int i = blockIdx.x * blockDim.x + threadIdx.x;
    if (i < DI * NS) g_negA[i] = -expf(A_log[i]) * LOG2E;
}

// ---------------------------------------------------------------- GEMM1 core
template <int WSTR>
__device__ __forceinline__ void gemm1_core(const float* __restrict__ w0,
                                           const float* __restrict__ xs,
                                           float* __restrict__ acc) {
    float wbuf[2][WCH];
    const float* wp = w0;
#pragma unroll
    for (int j = 0; j < WCH; j++) wbuf[0][j] = wp[j * WSTR];

#pragma unroll
    for (int c = 0; c < KCH / WCH; c++) {
        const int cur = c & 1;                 // compile-time
        if (c + 1 < KCH / WCH) {
            const float* wn = wp + WCH * WSTR;
#pragma unroll
            for (int j = 0; j < WCH; j++) wbuf[cur ^ 1][j] = wn[j * WSTR];
        }
#pragma unroll
        for (int j = 0; j < WCH; j++) {
            float w = wbuf[cur][j];
            const float4* xv4 = reinterpret_cast<const float4*>(xs + (c * WCH + j) * BT1);
#pragma unroll
            for (int q = 0; q < BT1 / 4; q++) {
                float4 xv = xv4[q];
                acc[4*q+0] += xv.x * w;
                acc[4*q+1] += xv.y * w;
                acc[4*q+2] += xv.z * w;
                acc[4*q+3] += xv.w * w;
            }
        }
        wp += WCH * WSTR;
    }
}

// ---------------------------------------------------------------- GEMM1
__global__ void __launch_bounds__(RX)
k_gemm1(const float* __restrict__ x,
        const float* __restrict__ Wd,
        const float* __restrict__ WB,
        const float* __restrict__ WC) {
    __shared__ float xs[KCH * BT1];         // [kk][bb]  8 KB
    const int r  = threadIdx.x;             // 0..191
    const int b0 = blockIdx.x * BT1;
    const int k0 = blockIdx.y * KCH;

    for (int i = r; i < KCH * BT1; i += RX) {
        int bb = i / KCH, kk = i - bb * KCH;
        xs[kk * BT1 + bb] = x[(b0 + bb) * DI + k0 + kk];
    }

    float acc[BT1];
#pragma unroll
    for (int i = 0; i < BT1; i++) acc[i] = 0.f;

    __syncthreads();

    if (r < 160) {
        gemm1_core<160>(Wd + r + k0 * 160, xs, acc);
    } else {
        const float* wb = (r < 176) ? (WB + (r - 160) + k0 * 16)
                                    : (WC + (r - 176) + k0 * 16);
        gemm1_core<16>(wb, xs, acc);
    }

    float* out = g_part + (blockIdx.y * BATCH + b0) * RX + r;
#pragma unroll
    for (int bb = 0; bb < BT1; bb++) out[bb * RX] = acc[bb];
}

// ---------------------------------------------------------------- reduce
__global__ void k_reduce() {
    int i = blockIdx.x * blockDim.x + threadIdx.x;    // float4 index
    if (i >= BATCH * RX / 4) return;
    const float4* p = reinterpret_cast<const float4*>(g_part) + i;
    float4 s = make_float4(0.f, 0.f, 0.f, 0.f);
#pragma unroll
    for (int ks = 0; ks < KS1; ks++) {
        float4 v = p[ks * (BATCH * RX / 4)];
        s.x += v.x; s.y += v.y; s.z += v.z; s.w += v.w;
    }
    reinterpret_cast<float4*>(g_xd)[i] = s;
}

// ---------------------------------------------------------------- fused GEMM2 + softplus + SSM
// Block = 16 batches x 128 d.  Wdt staged in double-buffered smem tiles
// (block reads Wdt once -> 53 MB total L2 traffic).  dt lives in smem only.
__global__ void __launch_bounds__(256)
k_fused3(const float* __restrict__ x,
         const float* __restrict__ h,
         const float* __restrict__ Wdt,
         const float* __restrict__ b_dt,
         const float* __restrict__ Dv,
         float* __restrict__ y) {
    __shared__ float sW[2][RCHF * DCHF];    // 2 x 8 KB
    __shared__ float sxd[RNK * BTF];        // [r][bb]  10 KB
    __shared__ float sBC[BTF * 2 * NS];     // per batch: B[16] | C[16]  2 KB
    __shared__ float sdt[BTF * DCHF];       // [bb][d]  8 KB
    __shared__ float sbc[BTF];
    const int tid  = threadIdx.x;           // 0..255
    const int d0   = blockIdx.x * DCHF;
    const int b0   = blockIdx.y * BTF;
    const int dloc = tid & (DCHF - 1);      // 0..127
    const int bh   = tid >> 7;              // batch half: 0/1

    // stage xd and BC
    for (int i = tid; i < RNK * BTF; i += 256) {
        int r = i >> 4, bb = i & 15;
        sxd[i] = g_xd[(b0 + bb) * RX + r];
    }
    for (int i = tid; i < BTF * 2 * NS; i += 256) {
        int bb = i >> 5, j = i & 31;
        sBC[i] = g_xd[(b0 + bb) * RX + 160 + j];
    }

    // stage Wdt chunk 0
    {
        const int rr = tid >> 5, f4 = tid & 31;
        const float* src = Wdt + d0;
        float4 v0 = *reinterpret_cast<const float4*>(src + rr * DI + f4 * 4);
        float4 v1 = *reinterpret_cast<const float4*>(src + (rr + 8) * DI + f4 * 4);
        *reinterpret_cast<float4*>(&sW[0][rr * DCHF + f4 * 4]) = v0;
        *reinterpret_cast<float4*>(&sW[0][(rr + 8) * DCHF + f4 * 4]) = v1;
    }
    __syncthreads();

    if (tid < BTF) {
        float s = 0.f;
#pragma unroll
        for (int n = 0; n < NS; n++) s += sBC[tid * 32 + n] * sBC[tid * 32 + NS + n];
        sbc[tid] = s;
    }

    // ---- Phase 1: GEMM2 over smem-staged Wdt, double-buffered
    float acc[8];
#pragma unroll
    for (int i = 0; i < 8; i++) acc[i] = 0.f;

#pragma unroll
    for (int c = 0; c < RNK / RCHF; c++) {          // 10 chunks
        const int cur = c & 1;
        if (c + 1 < RNK / RCHF) {
            const int rr = tid >> 5, f4 = tid & 31;
            const float* src = Wdt + (c + 1) * RCHF * DI + d0;
            float4 v0 = *reinterpret_cast<const float4*>(src + rr * DI + f4 * 4);
            float4 v1 = *reinterpret_cast<const float4*>(src + (rr + 8) * DI + f4 * 4);
            *reinterpret_cast<float4*>(&sW[cur ^ 1][rr * DCHF + f4 * 4]) = v0;
            *reinterpret_cast<float4*>(&sW[cur ^ 1][(rr + 8) * DCHF + f4 * 4]) = v1;
        }
#pragma unroll
        for (int rr = 0; rr < RCHF; rr++) {
            float w = sW[cur][rr * DCHF + dloc];
            const float4* xp = reinterpret_cast<const float4*>(
                sxd + (c * RCHF + rr) * BTF + bh * 8);
            float4 xa = xp[0], xb = xp[1];
            acc[0] += xa.x * w;  acc[1] += xa.y * w;
            acc[2] += xa.z * w;  acc[3] += xa.w * w;
            acc[4] += xb.x * w;  acc[5] += xb.y * w;
            acc[6] += xb.z * w;  acc[7] += xb.w * w;
        }
        __syncthreads();
    }

    {
        float bv = b_dt[d0 + dloc];
#pragma unroll
        for (int j = 0; j < 8; j++) {
            float z = acc[j] + bv;
            sdt[(bh * 8 + j) * DCHF + dloc] = (z > 20.f) ? z : log1pf(expf(z));
        }
    }
    __syncthreads();                        // sdt, sbc ready

    // ---- Phase 2: SSM readout, 4 lanes per d, batched h loads (MLP=4)
    const int q  = tid & 3;                 // n-quartet
    const int dl = tid >> 2;                // 0..63
    const float4* h4  = reinterpret_cast<const float4*>(h);
    const float4* na4 = reinterpret_cast<const float4*>(g_negA);

#pragma unroll
    for (int p = 0; p < DCHF / 64; p++) {
        const int dd = p * 64 + dl;
        const int dg = d0 + dd;
        float4 na  = na4[dg * (NS / 4) + q];
        float Dval = Dv[dg];

#pragma unroll
        for (int g = 0; g < BTF / 4; g++) {
            float4 hv[4];
            float dts[4];
#pragma unroll
            for (int j = 0; j < 4; j++)
                hv[j] = h4[((b0 + g * 4 + j) * DI + dg) * (NS / 4) + q];
#pragma unroll
            for (int j = 0; j < 4; j++)
                dts[j] = sdt[(g * 4 + j) * DCHF + dd];

#pragma unroll
            for (int j = 0; j < 4; j++) {
                const int bb = g * 4 + j;
                float4 Cq = *reinterpret_cast<const float4*>(sBC + bb * 32 + NS + 4 * q);
                float dtv = dts[j];
                float s = ex2(dtv * na.x) * hv[j].x * Cq.x
                        + ex2(dtv * na.y) * hv[j].y * Cq.y
                        + ex2(dtv * na.z) * hv[j].z * Cq.z
                        + ex2(dtv * na.w) * hv[j].w * Cq.w;
                s += __shfl_xor_sync(0xFFFFFFFF, s, 1);
                s += __shfl_xor_sync(0xFFFFFFFF, s, 2);
                if (q == 0) {
                    float xv = x[(b0 + bb) * DI + dg];
                    y[(b0 + bb) * DI + dg] = s + xv * (dtv * sbc[bb] + Dval);
                }
            }
        }
    }
}

// ----------------------------------------------------------------
extern "C" void kernel_launch(void* const* d_in, const int* in_sizes, int n_in,
                              void* d_out, int out_size) {
    const float* x    = (const float*)d_in[0];
    const float* h    = (const float*)d_in[1];
    const float* Wd   = (const float*)d_in[2];
    const float* Wdt  = (const float*)d_in[3];
    const float* bdt  = (const float*)d_in[4];
    const float* Alog = (const float*)d_in[5];
    const float* WB   = (const float*)d_in[6];
    const float* WC   = (const float*)d_in[7];
    const float* D    = (const float*)d_in[8];
    float* y = (float*)d_out;

    k_prep  <<<(DI * NS + 255) / 256, 256>>>(Alog);
    k_gemm1 <<<dim3(BATCH / BT1, KS1), RX>>>(x, Wd, WB, WC);
    k_reduce<<<(BATCH * RX / 4 + 255) / 256, 256>>>();
    k_fused3<<<dim3(DI / DCHF, BATCH / BTF), 256>>>(x, h, Wdt, bdt, D, y);
}

// round 11
// speedup vs baseline: 1.0537x; 1.0537x over previous
#include <cuda_runtime.h>
#include <math.h>

#define BATCH 256
#define DI    5120
#define RNK   160
#define NS    16
#define RX    192            // 160 (delta) + 16 (B) + 16 (C)

#define KS1   40             // split-K factor for GEMM1
#define KCH   (DI / KS1)     // 128
#define BT1   16             // batch tile GEMM1
#define WCH   16             // w prefetch chunk GEMM1

#define BTF   32             // batch tile fused kernel
#define DCHF  64             // d's per fused block
#define RCHF  16             // Wdt smem chunk (rows)

#define LOG2E 1.4426950408889634f

// ---- scratch (no dynamic allocation allowed) ----
__device__ float g_part[KS1 * BATCH * RX];   // GEMM1 split-K partials
__device__ float g_xdT[RNK * BATCH];         // delta proj, TRANSPOSED [r][b]
__device__ float g_bc[BATCH * 2 * NS];       // [b][ B[16] | C[16] ]
__device__ float g_negA[DI * NS];            // [d][n]: -exp(A_log)*log2e

__device__ __forceinline__ float ex2(float v) {
    float r;
    asm("ex2.approx.ftz.f32 %0, %1;" : "=f"(r) : "f"(v));
    return r;
}

// ---------------------------------------------------------------- prep
__global__ void k_prep(const float* __restrict__ A_log) {
    int i = blockIdx.x * blockDim.x + threadIdx.x;
    if (i < DI * NS) g_negA[i] = -expf(A_log[i]) * LOG2E;
}

// ---------------------------------------------------------------- GEMM1 core
template <int WSTR>
__device__ __forceinline__ void gemm1_core(const float* __restrict__ w0,
                                           const float* __restrict__ xs,
                                           float* __restrict__ acc) {
    float wbuf[2][WCH];
    const float* wp = w0;
#pragma unroll
    for (int j = 0; j < WCH; j++) wbuf[0][j] = wp[j * WSTR];

#pragma unroll
    for (int c = 0; c < KCH / WCH; c++) {
        const int cur = c & 1;                 // compile-time
        if (c + 1 < KCH / WCH) {
            const float* wn = wp + WCH * WSTR;
#pragma unroll
            for (int j = 0; j < WCH; j++) wbuf[cur ^ 1][j] = wn[j * WSTR];
        }
#pragma unroll
        for (int j = 0; j < WCH; j++) {
            float w = wbuf[cur][j];
            const float4* xv4 = reinterpret_cast<const float4*>(xs + (c * WCH + j) * BT1);
#pragma unroll
            for (int q = 0; q < BT1 / 4; q++) {
                float4 xv = xv4[q];
                acc[4*q+0] += xv.x * w;
                acc[4*q+1] += xv.y * w;
                acc[4*q+2] += xv.z * w;
                acc[4*q+3] += xv.w * w;
            }
        }
        wp += WCH * WSTR;
    }
}

// ---------------------------------------------------------------- GEMM1
__global__ void __launch_bounds__(RX)
k_gemm1(const float* __restrict__ x,
        const float* __restrict__ Wd,
        const float* __restrict__ WB,
        const float* __restrict__ WC) {
    __shared__ float xs[KCH * BT1];         // [kk][bb]  8 KB
    const int r  = threadIdx.x;             // 0..191
    const int b0 = blockIdx.x * BT1;
    const int k0 = blockIdx.y * KCH;

    for (int i = r; i < KCH * BT1; i += RX) {
        int bb = i / KCH, kk = i - bb * KCH;
        xs[kk * BT1 + bb] = x[(b0 + bb) * DI + k0 + kk];
    }

    float acc[BT1];
#pragma unroll
    for (int i = 0; i < BT1; i++) acc[i] = 0.f;

    __syncthreads();

    if (r < 160) {
        gemm1_core<160>(Wd + r + k0 * 160, xs, acc);
    } else {
        const float* wb = (r < 176) ? (WB + (r - 160) + k0 * 16)
                                    : (WC + (r - 176) + k0 * 16);
        gemm1_core<16>(wb, xs, acc);
    }

    float* out = g_part + (blockIdx.y * BATCH + b0) * RX + r;
#pragma unroll
    for (int bb = 0; bb < BT1; bb++) out[bb * RX] = acc[bb];
}

// ---------------------------------------------------------------- reduce
// Sums split-K partials; writes delta part TRANSPOSED [r][b], BC part [b][32].
__global__ void k_reduce() {
    int i = blockIdx.x * blockDim.x + threadIdx.x;
    if (i >= BATCH * RX) return;
    int b = i / RX, r = i - b * RX;
    float s = 0.f;
#pragma unroll
    for (int ks = 0; ks < KS1; ks++) s += g_part[ks * (BATCH * RX) + i];
    if (r < RNK) g_xdT[r * BATCH + b] = s;
    else         g_bc[b * 32 + (r - RNK)] = s;
}

// ---------------------------------------------------------------- fused GEMM2 + softplus + SSM
// Block = 32 batches x 64 d, 256 threads, grid (80, 8).
// Wdt smem-staged (26 MB total L2 traffic). dt never leaves smem.
// Phase 1: 4 threads per d x 8 batches each (acc[8]).
// Phase 2: 4 lanes per n-quartet per d; h loads coalesced 512B/warp.
__global__ void __launch_bounds__(256)
k_fused4(const float* __restrict__ x,
         const float* __restrict__ h,
         const float* __restrict__ Wdt,
         const float* __restrict__ b_dt,
         const float* __restrict__ Dv,
         float* __restrict__ y) {
    __shared__ float sW[2][RCHF * DCHF];    // 2 x 4 KB
    __shared__ float sxd[RNK * BTF];        // [r][bb]  20 KB
    __shared__ float sBC[BTF * 2 * NS];     // [bb][ B | C ]  4 KB
    __shared__ float sdt[BTF * DCHF];       // [bb][d]  8 KB
    __shared__ float sbc[BTF];
    const int tid = threadIdx.x;            // 0..255
    const int d0  = blockIdx.x * DCHF;
    const int b0  = blockIdx.y * BTF;

    // stage xd (coalesced: consecutive lanes -> consecutive b)
    for (int i = tid; i < RNK * BTF; i += 256) {
        int r = i >> 5, bb = i & 31;
        sxd[i] = g_xdT[r * BATCH + b0 + bb];
    }
    for (int i = tid; i < BTF * 2 * NS; i += 256) {
        int bb = i >> 5, j = i & 31;
        sBC[i] = g_bc[(b0 + bb) * 32 + j];
    }
    // stage Wdt chunk 0 (each thread one float4)
    {
        const int rr = tid >> 4, f4 = tid & 15;
        float4 v = *reinterpret_cast<const float4*>(Wdt + rr * DI + d0 + f4 * 4);
        *reinterpret_cast<float4*>(&sW[0][rr * DCHF + f4 * 4]) = v;
    }
    __syncthreads();

    if (tid < BTF) {
        float s = 0.f;
#pragma unroll
        for (int n = 0; n < NS; n++) s += sBC[tid * 32 + n] * sBC[tid * 32 + NS + n];
        sbc[tid] = s;
    }

    // ---- Phase 1: GEMM2 over smem Wdt (outer loop rolled: small code, low regs)
    const int dloc = tid & 63;              // d within block
    const int bq   = tid >> 6;              // batch octet 0..3
    float acc[8];
#pragma unroll
    for (int i = 0; i < 8; i++) acc[i] = 0.f;

    for (int c = 0; c < RNK / RCHF; c++) {          // 10 chunks
        const int cur = c & 1;
        if (c + 1 < RNK / RCHF) {
            const int rr = tid >> 4, f4 = tid & 15;
            float4 v = *reinterpret_cast<const float4*>(
                Wdt + ((c + 1) * RCHF + rr) * DI + d0 + f4 * 4);
            *reinterpret_cast<float4*>(&sW[cur ^ 1][rr * DCHF + f4 * 4]) = v;
        }
#pragma unroll
        for (int rr = 0; rr < RCHF; rr++) {
            float w = sW[cur][rr * DCHF + dloc];
            const float4* xp = reinterpret_cast<const float4*>(
                sxd + (c * RCHF + rr) * BTF + bq * 8);
            float4 xa = xp[0], xb = xp[1];
            acc[0] += xa.x * w;  acc[1] += xa.y * w;
            acc[2] += xa.z * w;  acc[3] += xa.w * w;
            acc[4] += xb.x * w;  acc[5] += xb.y * w;
            acc[6] += xb.z * w;  acc[7] += xb.w * w;
        }
        __syncthreads();
    }

    {
        float bv = b_dt[d0 + dloc];
#pragma unroll
        for (int j = 0; j < 8; j++) {
            float z = acc[j] + bv;
            sdt[(bq * 8 + j) * DCHF + dloc] = (z > 20.f) ? z : log1pf(expf(z));
        }
    }
    __syncthreads();                        // sdt, sbc ready

    // ---- Phase 2: SSM readout
    const int q  = tid & 3;                 // n-quartet
    const int dl = tid >> 2;                // 0..63 (all of DCHF)
    const int dg = d0 + dl;
    const float4* h4  = reinterpret_cast<const float4*>(h);
    float4 na  = reinterpret_cast<const float4*>(g_negA)[dg * (NS / 4) + q];
    float Dval = Dv[dg];

#pragma unroll 2
    for (int g = 0; g < BTF / 4; g++) {
        float4 hv[4];
        float dts[4];
#pragma unroll
        for (int j = 0; j < 4; j++)
            hv[j] = h4[((b0 + g * 4 + j) * DI + dg) * (NS / 4) + q];
#pragma unroll
        for (int j = 0; j < 4; j++)
            dts[j] = sdt[(g * 4 + j) * DCHF + dl];

#pragma unroll
        for (int j = 0; j < 4; j++) {
            const int bb = g * 4 + j;
            float4 Cq = *reinterpret_cast<const float4*>(sBC + bb * 32 + NS + 4 * q);
            float dtv = dts[j];
            float s = ex2(dtv * na.x) * hv[j].x * Cq.x
                    + ex2(dtv * na.y) * hv[j].y * Cq.y
                    + ex2(dtv * na.z) * hv[j].z * Cq.z
                    + ex2(dtv * na.w) * hv[j].w * Cq.w;
            s += __shfl_xor_sync(0xFFFFFFFF, s, 1);
            s += __shfl_xor_sync(0xFFFFFFFF, s, 2);
            if (q == 0) {
                float xv = x[(b0 + bb) * DI + dg];
                y[(b0 + bb) * DI + dg] = s + xv * (dtv * sbc[bb] + Dval);
            }
        }
    }
}

// ----------------------------------------------------------------
extern "C" void kernel_launch(void* const* d_in, const int* in_sizes, int n_in,
                              void* d_out, int out_size) {
    const float* x    = (const float*)d_in[0];
    const float* h    = (const float*)d_in[1];
    const float* Wd   = (const float*)d_in[2];
    const float* Wdt  = (const float*)d_in[3];
    const float* bdt  = (const float*)d_in[4];
    const float* Alog = (const float*)d_in[5];
    const float* WB   = (const float*)d_in[6];
    const float* WC   = (const float*)d_in[7];
    const float* D    = (const float*)d_in[8];
    float* y = (float*)d_out;

    k_prep  <<<(DI * NS + 255) / 256, 256>>>(Alog);
    k_gemm1 <<<dim3(BATCH / BT1, KS1), RX>>>(x, Wd, WB, WC);
    k_reduce<<<(BATCH * RX + 255) / 256, 256>>>();
    k_fused4<<<dim3(DI / DCHF, BATCH / BTF), 256>>>(x, h, Wdt, bdt, D, y);
}

// round 12
// speedup vs baseline: 1.1117x; 1.0550x over previous
#include <cuda_runtime.h>
#include <math.h>

#define BATCH 256
#define DI    5120
#define RNK   160
#define NS    16
#define RX    192            // 160 (delta) + 16 (B) + 16 (C)

#define KS1   40             // split-K factor for GEMM1
#define KCH   (DI / KS1)     // 128
#define BT1   8              // batch tile GEMM1 (8 -> 1280 blocks, 2x parallelism)
#define WCH   16             // w prefetch chunk GEMM1

#define BT2   4              // batch tile fused kernel
#define DCH2  256            // d's (= threads) per fused block
#define RCH   8              // Wdt prefetch chunk

#define LOG2E 1.4426950408889634f

// ---- scratch (no dynamic allocation allowed) ----
__device__ float g_part[KS1 * BATCH * RX];   // GEMM1 split-K partials
__device__ float g_xd[BATCH * RX];           // [xd | Bp | C]
__device__ float g_negA[DI * NS];            // [d][n]: -exp(A_log)*log2e

// ---------------------------------------------------------------- prep
__global__ void k_prep(const float* __restrict__ A_log) {
    int i = blockIdx.x * blockDim.x + threadIdx.x;
    if (i < DI * NS) g_negA[i] = -expf(A_log[i]) * LOG2E;
}

// ---------------------------------------------------------------- GEMM1 core
template <int WSTR>
__device__ __forceinline__ void gemm1_core(const float* __restrict__ w0,
                                           const float* __restrict__ xs,
                                           float* __restrict__ acc) {
    float wbuf[2][WCH];
    const float* wp = w0;
#pragma unroll
    for (int j = 0; j < WCH; j++) wbuf[0][j] = wp[j * WSTR];

#pragma unroll
    for (int c = 0; c < KCH / WCH; c++) {
        const int cur = c & 1;                 // compile-time
        if (c + 1 < KCH / WCH) {
            const float* wn = wp + WCH * WSTR;
#pragma unroll
            for (int j = 0; j < WCH; j++) wbuf[cur ^ 1][j] = wn[j * WSTR];
        }
#pragma unroll
        for (int j = 0; j < WCH; j++) {
            float w = wbuf[cur][j];
            const float4* xv4 = reinterpret_cast<const float4*>(xs + (c * WCH + j) * BT1);
#pragma unroll
            for (int q = 0; q < BT1 / 4; q++) {
                float4 xv = xv4[q];
                acc[4*q+0] += xv.x * w;
                acc[4*q+1] += xv.y * w;
                acc[4*q+2] += xv.z * w;
                acc[4*q+3] += xv.w * w;
            }
        }
        wp += WCH * WSTR;
    }
}

// ---------------------------------------------------------------- GEMM1
__global__ void __launch_bounds__(RX)
k_gemm1(const float* __restrict__ x,
        const float* __restrict__ Wd,
        const float* __restrict__ WB,
        const float* __restrict__ WC) {
    __shared__ float xs[KCH * BT1];         // [kk][bb]  4 KB
    const int r  = threadIdx.x;             // 0..191
    const int b0 = blockIdx.x * BT1;
    const int k0 = blockIdx.y * KCH;

    for (int i = r; i < KCH * BT1; i += RX) {
        int bb = i / KCH, kk = i - bb * KCH;
        xs[kk * BT1 + bb] = x[(b0 + bb) * DI + k0 + kk];
    }

    float acc[BT1];
#pragma unroll
    for (int i = 0; i < BT1; i++) acc[i] = 0.f;

    __syncthreads();

    if (r < 160) {
        gemm1_core<160>(Wd + r + k0 * 160, xs, acc);
    } else {
        const float* wb = (r < 176) ? (WB + (r - 160) + k0 * 16)
                                    : (WC + (r - 176) + k0 * 16);
        gemm1_core<16>(wb, xs, acc);
    }

    float* out = g_part + (blockIdx.y * BATCH + b0) * RX + r;
#pragma unroll
    for (int bb = 0; bb < BT1; bb++) out[bb * RX] = acc[bb];
}

// ---------------------------------------------------------------- reduce
__global__ void k_reduce() {
    int i = blockIdx.x * blockDim.x + threadIdx.x;    // float4 index
    if (i >= BATCH * RX / 4) return;
    const float4* p = reinterpret_cast<const float4*>(g_part) + i;
    float4 s = make_float4(0.f, 0.f, 0.f, 0.f);
#pragma unroll
    for (int ks = 0; ks < KS1; ks++) {
        float4 v = p[ks * (BATCH * RX / 4)];
        s.x += v.x; s.y += v.y; s.z += v.z; s.w += v.w;
    }
    reinterpret_cast<float4*>(g_xd)[i] = s;
}

// ---------------------------------------------------------------- fused GEMM2 + softplus + SSM
// (exact round-9 structure: barrier-free private Wdt prefetch; best measured)
__global__ void __launch_bounds__(DCH2)
k_fused2(const float* __restrict__ x,
         const float* __restrict__ h,
         const float* __restrict__ Wdt,
         const float* __restrict__ b_dt,
         const float* __restrict__ Dv,
         float* __restrict__ y) {
    __shared__ float xds[RNK * BT2];        // [r][bb]   2.5 KB
    __shared__ float sdt[BT2 * DCH2];       // [bb][d]   4 KB
    __shared__ float sBC[BT2 * 2 * NS];     // per batch: B[16] | C[16]
    __shared__ float sbc[BT2];              // dot(B,C) per batch
    const int tid = threadIdx.x;            // 0..255
    const int d   = blockIdx.x * DCH2 + tid;
    const int b0  = blockIdx.y * BT2;

    for (int i = tid; i < RNK * BT2; i += DCH2) {
        int bb = i / RNK, r = i - bb * RNK;
        xds[r * BT2 + bb] = g_xd[(b0 + bb) * RX + r];
    }
    if (tid < BT2 * 2 * NS) {
        int bb = tid >> 5, j = tid & 31;
        sBC[tid] = g_xd[(b0 + bb) * RX + 160 + j];
    }
    __syncthreads();

    if (tid < BT2) {
        float s = 0.f;
#pragma unroll
        for (int n = 0; n < NS; n++) s += sBC[tid * 32 + n] * sBC[tid * 32 + NS + n];
        sbc[tid] = s;
    }

    // ---- Phase 1: GEMM2 (register double-buffered W, fully unrolled)
    float acc[BT2];
#pragma unroll
    for (int i = 0; i < BT2; i++) acc[i] = 0.f;

    const float* wp = Wdt + d;
    float wbuf[2][RCH];
#pragma unroll
    for (int j = 0; j < RCH; j++) wbuf[0][j] = wp[j * DI];

#pragma unroll
    for (int c = 0; c < RNK / RCH; c++) {
        const int cur = c & 1;                 // compile-time
        if (c + 1 < RNK / RCH) {
            const float* wn = wp + RCH * DI;
#pragma unroll
            for (int j = 0; j < RCH; j++) wbuf[cur ^ 1][j] = wn[j * DI];
        }
        const int rbase = c * RCH;
#pragma unroll
        for (int j = 0; j < RCH; j++) {
            float w = wbuf[cur][j];
            float4 xv = *reinterpret_cast<const float4*>(xds + (rbase + j) * BT2);
            acc[0] += xv.x * w;  acc[1] += xv.y * w;
            acc[2] += xv.z * w;  acc[3] += xv.w * w;
        }
        wp += RCH * DI;
    }

    float bv = b_dt[d];
#pragma unroll
    for (int bb = 0; bb < BT2; bb++) {
        float z = acc[bb] + bv;
        sdt[bb * DCH2 + tid] = (z > 20.f) ? z : log1pf(expf(z));
    }
    __syncthreads();                        // sdt, sbc ready

    // ---- Phase 2: SSM readout, 4 lanes per d, batched loads (MLP>=4)
    const int dl = tid >> 2;                // 0..63
    const int q  = tid & 3;                 // n-quartet
    const float4* h4  = reinterpret_cast<const float4*>(h);
    const float4* na4 = reinterpret_cast<const float4*>(g_negA);

#pragma unroll
    for (int p = 0; p < DCH2 / 64; p++) {
        const int dd = p * 64 + dl;
        const int dg = blockIdx.x * DCH2 + dd;

        // issue all independent loads first
        float4 na = na4[dg * (NS / 4) + q];
        float4 hv[BT2];
#pragma unroll
        for (int bb = 0; bb < BT2; bb++)
            hv[bb] = h4[((b0 + bb) * DI + dg) * (NS / 4) + q];
        float dts[BT2];
#pragma unroll
        for (int bb = 0; bb < BT2; bb++) dts[bb] = sdt[bb * DCH2 + dd];
        float Dval = Dv[dg];

#pragma unroll
        for (int bb = 0; bb < BT2; bb++) {
            float4 Cq = *reinterpret_cast<const float4*>(sBC + bb * 32 + NS + 4 * q);
            float dtv = dts[bb];
            float s = exp2f(dtv * na.x) * hv[bb].x * Cq.x
                    + exp2f(dtv * na.y) * hv[bb].y * Cq.y
                    + exp2f(dtv * na.z) * hv[bb].z * Cq.z
                    + exp2f(dtv * na.w) * hv[bb].w * Cq.w;
            s += __shfl_xor_sync(0xFFFFFFFF, s, 1);
            s += __shfl_xor_sync(0xFFFFFFFF, s, 2);
            if (q == 0) {
                float xv = x[(b0 + bb) * DI + dg];
                y[(b0 + bb) * DI + dg] = s + xv * (dtv * sbc[bb] + Dval);
            }
        }
    }
}

// ----------------------------------------------------------------
extern "C" void kernel_launch(void* const* d_in, const int* in_sizes, int n_in,
                              void* d_out, int out_size) {
    const float* x    = (const float*)d_in[0];
    const float* h    = (const float*)d_in[1];
    const float* Wd   = (const float*)d_in[2];
    const float* Wdt  = (const float*)d_in[3];
    const float* bdt  = (const float*)d_in[4];
    const float* Alog = (const float*)d_in[5];
    const float* WB   = (const float*)d_in[6];
    const float* WC   = (const float*)d_in[7];
    const float* D    = (const float*)d_in[8];
    float* y = (float*)d_out;

    k_prep  <<<(DI * NS + 255) / 256, 256>>>(Alog);
    k_gemm1 <<<dim3(BATCH / BT1, KS1), RX>>>(x, Wd, WB, WC);
    k_reduce<<<(BATCH * RX / 4 + 255) / 256, 256>>>();
    k_fused2<<<dim3(DI / DCH2, BATCH / BT2), DCH2>>>(x, h, Wdt, bdt, D, y);
}